// round 16
// baseline (speedup 1.0000x reference)
#include <cuda_runtime.h>
#include <cstdint>

// ---------------------------------------------------------------------------
// Shapes (fixed): B=4, N=M=P=2048, NS=1024
// out[b,n,m] = S + 0.5*dist(pc1_0[b,n], pc2[b,m])
// S = conf + 0.5*cd(flat pc1_0||pc2) + seed_cd(flat pc1_1||pc2)
//
// nn_dual2: each chamfer matrix computed ONCE (row-min + col-min), no atomics,
// writing the SAME scratch layout as the proven R13 build:
//  slot0: 16*8192  @0       cd dir1 (per pc2 j,   slab = 512-pt pc1_0 chunk)
//  slot1: 16*8192  @131072  cd dir2 (per pc1_0 a, slab = 512-pt pc2 seg)
//  slot2:  8*8192  @262144  seed d1 (per pc2 j,   slab = 512-pt pc1_1 chunk)
//  slot3: 16*4096  @327680  seed d2 (per pc1_1 a, slab = 512-pt pc2 seg)
//  slot4: 16*2048  @393216  conf    (per-b row b*4+rc, rc = 512-pt pc2 chunk)
// ---------------------------------------------------------------------------

__device__ float g_part[425984];
__device__ float g_scal[3];    // [0]=cd [1]=seed [2]=conf

__device__ __forceinline__ float fsqrt_ap(float x) {
    float r; asm("sqrt.approx.f32 %0,%1;" : "=f"(r) : "f"(x)); return r;
}

// -------------------------------- init --------------------------------------
__global__ void init_kernel() {
    if (threadIdx.x < 3) g_scal[threadIdx.x] = 0.0f;
}

// ------------------------- dual-min tiled NN pass ----------------------------
// 384 blocks x 256 threads (tx=16, ty=16).
// Block = (cloud, 512-A-chunk, 512-B-seg). sA/sB fully staged. Outer loop:
// 4 A-subchunks of 128 (8 rows/thread in regs, amin accumulated over both
// B tiles -> dir2 slab write per subchunk). Inner: 2 B tiles of 256; per-col
// min via shfl(ty-pair)+sRed, accumulated into colmin[512] -> dir1 at end.
__global__ void __launch_bounds__(256) nn_dual2(const float* __restrict__ pc10,
                                                const float* __restrict__ pc11,
                                                const float* __restrict__ pc2)
{
    __shared__ float4 sA[512];
    __shared__ float4 sB[512];
    __shared__ float  sRed[8][256];
    __shared__ float  colmin[512];
    const int t  = threadIdx.x;
    const int tx = t & 15, ty = t >> 4;
    int l = blockIdx.x;

    const float* A; float* d1slot; float* d2slot; int achunk, seg;
    if (l < 256) {             // cd: A = pc1_0 (16 chunks x 16 segs)
        achunk = l >> 4; seg = l & 15; A = pc10;
        d1slot = g_part +          achunk * 8192;
        d2slot = g_part + 131072 + seg * 8192;
    } else {                   // seed: A = pc1_1 (8 chunks x 16 segs)
        l -= 256;
        achunk = l >> 4; seg = l & 15; A = pc11;
        d1slot = g_part + 262144 + achunk * 8192;
        d2slot = g_part + 327680 + seg * 4096;
    }
    const int abase = achunk * 512;
    const int bbase = seg * 512;

    // ---- stage A chunk, B seg (2 pts per thread each), init colmin ----
    #pragma unroll
    for (int j = 0; j < 2; j++) {
        const int idx = t + j * 256;
        const float* ap = A   + 3 * (abase + idx);
        const float* bp = pc2 + 3 * (bbase + idx);
        const float axv = ap[0], ayv = ap[1], azv = ap[2];
        const float bxv = bp[0], byv = bp[1], bzv = bp[2];
        sA[idx] = make_float4(axv, ayv, azv, axv * axv + ayv * ayv + azv * azv);
        sB[idx] = make_float4(bxv, byv, bzv, bxv * bxv + byv * byv + bzv * bzv);
        colmin[idx] = 3.0e38f;
    }
    __syncthreads();

    // ---- 4 A-subchunks of 128 ----
    for (int sub = 0; sub < 4; sub++) {
        float nax[8], nay[8], naz[8], aa[8], amin[8];
        #pragma unroll
        for (int i = 0; i < 8; i++) {
            const float4 a = sA[sub * 128 + ty * 8 + i];   // tx-broadcast
            nax[i] = -2.f * a.x; nay[i] = -2.f * a.y; naz[i] = -2.f * a.z;
            aa[i] = a.w;
            amin[i] = 3.0e38f;
        }

        #pragma unroll
        for (int tile = 0; tile < 2; tile++) {
            __syncthreads();   // sRed free (prev reduce done)
            #pragma unroll 4
            for (int j0 = 0; j0 < 16; j0++) {
                const float4 b = sB[tile * 256 + j0 * 16 + tx];
                float bm = 3.0e38f;
                #pragma unroll
                for (int i = 0; i < 8; i++) {
                    const float d = fmaf(nax[i], b.x, fmaf(nay[i], b.y,
                                    fmaf(naz[i], b.z, b.w)));
                    amin[i] = fminf(amin[i], d);     // + aa folded at write
                    bm = fminf(bm, d + aa[i]);       // true d2 for col-min
                }
                bm = fminf(bm, __shfl_xor_sync(0xffffffffu, bm, 16));
                if ((ty & 1) == 0) sRed[ty >> 1][j0 * 16 + tx] = bm;
            }
            __syncthreads();   // sRed complete
            {   // 8-way column reduce, accumulate into colmin
                float m = sRed[0][t];
                #pragma unroll
                for (int k = 1; k < 8; k++) m = fminf(m, sRed[k][t]);
                const int j = tile * 256 + t;
                colmin[j] = fminf(colmin[j], m);
            }
        }

        // ---- dir2 write for this subchunk: reduce amin across 16 tx lanes ----
        #pragma unroll
        for (int i = 0; i < 8; i++) {
            float v = amin[i];
            v = fminf(v, __shfl_xor_sync(0xffffffffu, v, 1));
            v = fminf(v, __shfl_xor_sync(0xffffffffu, v, 2));
            v = fminf(v, __shfl_xor_sync(0xffffffffu, v, 4));
            v = fminf(v, __shfl_xor_sync(0xffffffffu, v, 8));
            if (tx == 0)
                d2slot[abase + sub * 128 + ty * 8 + i] =
                    fmaxf(v + aa[i], 0.0f);
        }
    }

    __syncthreads();   // colmin complete
    #pragma unroll
    for (int j = 0; j < 2; j++) {
        const int idx = t + j * 256;
        d1slot[bbase + idx] = fmaxf(colmin[idx], 0.0f);
    }
}

// --------------------------- conf NN pass (1-dir) ----------------------------
// 64 blocks x 256 threads: per-b, q=pc3 over R=pc2; writes slot4 scratch.
__global__ void __launch_bounds__(256) conf_kernel(const float* __restrict__ pc2,
                                                   const float* __restrict__ pc3)
{
    __shared__ float4 tile[512];
    const int t = threadIdx.x;
    const int l = blockIdx.x;
    const int b = l >> 4;
    const int r = l & 15;
    const int qb = r >> 2, rc = r & 3;
    const float* Q = pc3 + b * 6144;
    const float* R = pc2 + b * 6144;
    float* part = g_part + 393216 + (b * 4 + rc) * 2048 + qb * 512;

    {
        const float* rp = R + (size_t)rc * 1536;
        #pragma unroll
        for (int j = 0; j < 2; j++) {
            const int idx = t + j * 256;
            const float x = rp[3 * idx], y = rp[3 * idx + 1], z = rp[3 * idx + 2];
            tile[idx] = make_float4(x, y, z, x * x + y * y + z * z);
        }
    }

    const int q0 = qb * 512 + t;
    const int q1 = q0 + 256;
    const float ax0 = Q[3 * q0], ay0 = Q[3 * q0 + 1], az0 = Q[3 * q0 + 2];
    const float ax1 = Q[3 * q1], ay1 = Q[3 * q1 + 1], az1 = Q[3 * q1 + 2];
    const float a20 = ax0 * ax0 + ay0 * ay0 + az0 * az0;
    const float a21 = ax1 * ax1 + ay1 * ay1 + az1 * az1;
    const float nax0 = -2.f * ax0, nay0 = -2.f * ay0, naz0 = -2.f * az0;
    const float nax1 = -2.f * ax1, nay1 = -2.f * ay1, naz1 = -2.f * az1;

    float m0a = 3.0e38f, m0b = 3.0e38f, m1a = 3.0e38f, m1b = 3.0e38f;
    __syncthreads();

    #pragma unroll 4
    for (int g = 0; g < 512; g += 2) {
        const float4 r0 = tile[g];
        const float4 r1 = tile[g + 1];
        m0a = fminf(m0a, fmaf(nax0, r0.x, fmaf(nay0, r0.y, fmaf(naz0, r0.z, r0.w))));
        m1a = fminf(m1a, fmaf(nax1, r0.x, fmaf(nay1, r0.y, fmaf(naz1, r0.z, r0.w))));
        m0b = fminf(m0b, fmaf(nax0, r1.x, fmaf(nay0, r1.y, fmaf(naz0, r1.z, r1.w))));
        m1b = fminf(m1b, fmaf(nax1, r1.x, fmaf(nay1, r1.y, fmaf(naz1, r1.z, r1.w))));
    }

    part[t]       = fmaxf(fminf(m0a, m0b) + a20, 0.0f);
    part[t + 256] = fmaxf(fminf(m1a, m1b) + a21, 0.0f);
}

// ------------------------------ finalize ------------------------------------
// R13-proven structure: 36864 threads reduce slabs -> sqrt -> weighted sums.
__global__ void __launch_bounds__(256) finalize_kernel(const float* __restrict__ pc13)
{
    __shared__ float s[3];
    if (threadIdx.x < 3) s[threadIdx.x] = 0.0f;
    __syncthreads();

    const int i = blockIdx.x * 256 + threadIdx.x;
    float val; int cat;
    if (i < 8192) {                     // cd dir1
        float m = 3.0e38f;
        #pragma unroll
        for (int c = 0; c < 16; c++) m = fminf(m, g_part[c * 8192 + i]);
        val = sqrtf(m) * (1.0f / 8192.0f); cat = 0;
    } else if (i < 16384) {             // cd dir2
        const int q = i - 8192; float m = 3.0e38f;
        #pragma unroll
        for (int c = 0; c < 16; c++) m = fminf(m, g_part[131072 + c * 8192 + q]);
        val = sqrtf(m) * (1.0f / 8192.0f); cat = 0;
    } else if (i < 24576) {             // seed dir1
        const int q = i - 16384; float m = 3.0e38f;
        #pragma unroll
        for (int c = 0; c < 8; c++) m = fminf(m, g_part[262144 + c * 8192 + q]);
        val = sqrtf(m) * (1.0f / 8192.0f); cat = 1;
    } else if (i < 28672) {             // seed dir2
        const int q = i - 24576; float m = 3.0e38f;
        #pragma unroll
        for (int c = 0; c < 16; c++) m = fminf(m, g_part[327680 + c * 4096 + q]);
        val = sqrtf(m) * (1.0f / 4096.0f); cat = 1;
    } else {                            // confidence
        const int q = i - 28672;        // b*2048 + p
        const int b = q >> 11, p = q & 2047;
        float m = 3.0e38f;
        #pragma unroll
        for (int c = 0; c < 4; c++) m = fminf(m, g_part[393216 + (b * 4 + c) * 2048 + p]);
        const float gt = expf(-sqrtf(m));
        const float df = pc13[q] - gt;
        val = df * df * (1.0f / 8192.0f); cat = 2;
    }
    atomicAdd(&s[cat], val);
    __syncthreads();
    if (threadIdx.x < 3) atomicAdd(&g_scal[threadIdx.x], s[threadIdx.x]);
}

// ------------------------------ out kernel ----------------------------------
// R13-proven (12.9us): 2048 blocks x 256 threads, block = (b, col-half, 8-row
// chunk), 4 pc2 points/thread, queries pre-staged, MUFU sqrt, STG.128/row.
__global__ void __launch_bounds__(256) out_kernel(const float* __restrict__ pc10,
                                                  const float* __restrict__ pc2,
                                                  float* __restrict__ out)
{
    __shared__ float4 qs[8];             // per n: {nax, nay, naz, a2}
    const int t = threadIdx.x;
    const int b    = blockIdx.x >> 9;
    const int half = (blockIdx.x >> 8) & 1;
    const int nc   = blockIdx.x & 255;
    const int nbase = b * 2048 + nc * 8;
    const int mbase = half * 1024 + t * 4;

    float Gx[4], Gy[4], Gz[4], Gr[4];
    {
        float F[12];
        const float4* rp = (const float4*)(pc2 + (size_t)b * 6144 + mbase * 3);
        #pragma unroll
        for (int j = 0; j < 3; j++) {
            const float4 f = rp[j];
            F[4 * j] = f.x; F[4 * j + 1] = f.y;
            F[4 * j + 2] = f.z; F[4 * j + 3] = f.w;
        }
        #pragma unroll
        for (int g = 0; g < 4; g++) {
            Gx[g] = F[3 * g]; Gy[g] = F[3 * g + 1]; Gz[g] = F[3 * g + 2];
            Gr[g] = Gx[g] * Gx[g] + Gy[g] * Gy[g] + Gz[g] * Gz[g];
        }
    }

    if (t < 8) {
        const int n = nbase + t;
        const float x = pc10[3 * n], y = pc10[3 * n + 1], z = pc10[3 * n + 2];
        qs[t] = make_float4(-2.f * x, -2.f * y, -2.f * z, x * x + y * y + z * z);
    }
    const float S = g_scal[2] + 0.5f * g_scal[0] + g_scal[1];
    __syncthreads();

    float* orow = out + (size_t)nbase * 2048 + mbase;
    #pragma unroll
    for (int n = 0; n < 8; n++) {
        const float4 q = qs[n];
        float res[4];
        #pragma unroll
        for (int g = 0; g < 4; g++) {
            const float d2 = fmaf(q.x, Gx[g], fmaf(q.y, Gy[g],
                             fmaf(q.z, Gz[g], Gr[g] + q.w)));
            res[g] = fmaf(0.5f, fsqrt_ap(fmaxf(d2, 0.0f)), S);
        }
        *(float4*)orow = make_float4(res[0], res[1], res[2], res[3]);
        orow += 2048;
    }
}

// ------------------------------ launcher ------------------------------------
extern "C" void kernel_launch(void* const* d_in, const int* in_sizes, int n_in,
                              void* d_out, int out_size)
{
    const float* pc10 = (const float*)d_in[0];
    const float* pc11 = (const float*)d_in[1];
    const float* pc13 = (const float*)d_in[2];
    const float* pc2  = (const float*)d_in[3];
    const float* pc3  = (const float*)d_in[4];
    float* out = (float*)d_out;

    init_kernel<<<1, 32>>>();
    nn_dual2<<<384, 256>>>(pc10, pc11, pc2);
    conf_kernel<<<64, 256>>>(pc2, pc3);
    finalize_kernel<<<144, 256>>>(pc13);
    out_kernel<<<2048, 256>>>(pc10, pc2, out);
}

// round 17
// speedup vs baseline: 1.2216x; 1.2216x over previous
#include <cuda_runtime.h>
#include <cstdint>

// ---------------------------------------------------------------------------
// Shapes (fixed): B=4, N=M=P=2048, NS=1024
// out[b,n,m] = S + 0.5*dist(pc1_0[b,n], pc2[b,m])
// S = conf + 0.5*cd(flat pc1_0||pc2) + seed_cd(flat pc1_1||pc2)
//
// R13-proven nn_fused (4 queries/thread) + R13 out_kernel + NEW parallel
// finalize (the old one was 14.4us latency-bound at occ 12%).
// ---------------------------------------------------------------------------

// partial min-d2 scratch (chunk-major):
//  slot0: 16*8192  @0       cd dir1 (q=pc2,  R=pc1_0)
//  slot1: 16*8192  @131072  cd dir2 (q=pc1_0,R=pc2)
//  slot2:  8*8192  @262144  seed d1 (q=pc2,  R=pc1_1)
//  slot3: 16*4096  @327680  seed d2 (q=pc1_1,R=pc2)
//  slot4: 16*2048  @393216  conf    (per-b:  q=pc3,  R=pc2)
__device__ float g_part[425984];
__device__ float g_scal[3];    // [0]=cd [1]=seed [2]=conf

__device__ __forceinline__ float fsqrt_ap(float x) {
    float r; asm("sqrt.approx.f32 %0,%1;" : "=f"(r) : "f"(x)); return r;
}

// -------------------------------- init --------------------------------------
__global__ void init_kernel() {
    if (threadIdx.x < 3) g_scal[threadIdx.x] = 0.0f;
}

// --------------------------- fused NN min pass -------------------------------
// R13-proven: 416 blocks x 256 threads. Block = (task, 1024-query block,
// 512-R chunk). 4 queries/thread: each tile[g] LDS.128 serves 4 pairs.
__global__ void __launch_bounds__(256) nn_fused(const float* __restrict__ pc10,
                                                const float* __restrict__ pc11,
                                                const float* __restrict__ pc2,
                                                const float* __restrict__ pc3)
{
    __shared__ float4 tile[512];
    const int t = threadIdx.x;
    int l = blockIdx.x;

    const float* Q; const float* R; float* part; int qb, rc;
    if (l < 128)      {           // cd dir1: q=pc2 (8192), R=pc1_0 (16 chunks)
        qb = l >> 4; rc = l & 15; Q = pc2;  R = pc10;
        part = g_part +          rc * 8192 + qb * 1024;
    } else if (l < 256) {         // cd dir2: q=pc1_0 (8192), R=pc2 (16 chunks)
        l -= 128; qb = l >> 4; rc = l & 15; Q = pc10; R = pc2;
        part = g_part + 131072 + rc * 8192 + qb * 1024;
    } else if (l < 320) {         // seed d1: q=pc2 (8192), R=pc1_1 (8 chunks)
        l -= 256; qb = l >> 3; rc = l & 7;  Q = pc2;  R = pc11;
        part = g_part + 262144 + rc * 8192 + qb * 1024;
    } else if (l < 384) {         // seed d2: q=pc1_1 (4096), R=pc2 (16 chunks)
        l -= 320; qb = l >> 4; rc = l & 15; Q = pc11; R = pc2;
        part = g_part + 327680 + rc * 4096 + qb * 1024;
    } else {                      // conf: per-b, q=pc3 (2048), R=pc2 (4 chunks)
        l -= 384; const int b = l >> 3; const int r = l & 7;
        qb = r >> 2; rc = r & 3;
        Q = pc3 + b * 6144; R = pc2 + b * 6144;
        part = g_part + 393216 + (b * 4 + rc) * 2048 + qb * 1024;
    }

    // ---- stage chunk: 2 points per thread ----
    {
        const float* rp = R + (size_t)rc * 1536;   // 512 pts * 3 floats
        #pragma unroll
        for (int j = 0; j < 2; j++) {
            const int idx = t + j * 256;
            const float x = rp[3 * idx], y = rp[3 * idx + 1], z = rp[3 * idx + 2];
            tile[idx] = make_float4(x, y, z, x * x + y * y + z * z);
        }
    }

    // ---- four queries per thread ----
    float nax[4], nay[4], naz[4], a2[4], mn[4];
    #pragma unroll
    for (int k = 0; k < 4; k++) {
        const int q = qb * 1024 + t + k * 256;
        const float ax = Q[3 * q], ay = Q[3 * q + 1], az = Q[3 * q + 2];
        a2[k] = ax * ax + ay * ay + az * az;
        nax[k] = -2.f * ax; nay[k] = -2.f * ay; naz[k] = -2.f * az;
        mn[k] = 3.0e38f;
    }

    __syncthreads();

    #pragma unroll 8
    for (int g = 0; g < 512; g++) {
        const float4 r = tile[g];
        #pragma unroll
        for (int k = 0; k < 4; k++) {
            const float d2 = fmaf(nax[k], r.x, fmaf(nay[k], r.y,
                             fmaf(naz[k], r.z, r.w)));
            mn[k] = fminf(mn[k], d2);
        }
    }

    #pragma unroll
    for (int k = 0; k < 4; k++)
        part[t + k * 256] = fmaxf(mn[k] + a2[k], 0.0f);
}

// --------------------------- parallel finalize -------------------------------
// 2304 blocks x 256 threads = 589824 threads: one per (query, chunk-lane).
// q = gid >> 4, c = gid & 15. One LDG per thread, 16-lane shfl min, lane 0
// does sqrt/exp + weighted smem atomicAdd -> global atomicAdd.
__global__ void __launch_bounds__(256) finalize_kernel(const float* __restrict__ pc13)
{
    __shared__ float s[3];
    if (threadIdx.x < 3) s[threadIdx.x] = 0.0f;
    __syncthreads();

    const int gid = blockIdx.x * 256 + threadIdx.x;
    const int q = gid >> 4;
    const int c = gid & 15;

    int addr; int nch; int cat; float w; int conf_q = 0;
    if (q < 8192)       { addr =          c * 8192 + q;           nch = 16; cat = 0; w = 1.0f / 8192.0f; }
    else if (q < 16384) { addr = 131072 + c * 8192 + (q - 8192);  nch = 16; cat = 0; w = 1.0f / 8192.0f; }
    else if (q < 24576) { addr = 262144 + c * 8192 + (q - 16384); nch = 8;  cat = 1; w = 1.0f / 8192.0f; }
    else if (q < 28672) { addr = 327680 + c * 4096 + (q - 24576); nch = 16; cat = 1; w = 1.0f / 4096.0f; }
    else {
        conf_q = q - 28672;                       // b*2048 + p
        const int b = conf_q >> 11, p = conf_q & 2047;
        addr = 393216 + b * 8192 + c * 2048 + p;  nch = 4;  cat = 2; w = 1.0f / 8192.0f;
    }

    float m = (c < nch) ? g_part[addr] : 3.0e38f;
    m = fminf(m, __shfl_xor_sync(0xffffffffu, m, 1));
    m = fminf(m, __shfl_xor_sync(0xffffffffu, m, 2));
    m = fminf(m, __shfl_xor_sync(0xffffffffu, m, 4));
    m = fminf(m, __shfl_xor_sync(0xffffffffu, m, 8));

    if (c == 0) {
        float val;
        if (cat == 2) {
            const float gt = expf(-sqrtf(m));
            const float df = pc13[conf_q] - gt;
            val = df * df * w;
        } else {
            val = sqrtf(m) * w;
        }
        atomicAdd(&s[cat], val);
    }
    __syncthreads();
    if (threadIdx.x < 3) atomicAdd(&g_scal[threadIdx.x], s[threadIdx.x]);
}

// ------------------------------ out kernel ----------------------------------
// R13-proven (12.9us): 2048 blocks x 256 threads, block = (b, col-half, 8-row
// chunk), 4 pc2 points/thread, queries pre-staged, MUFU sqrt, STG.128/row.
__global__ void __launch_bounds__(256) out_kernel(const float* __restrict__ pc10,
                                                  const float* __restrict__ pc2,
                                                  float* __restrict__ out)
{
    __shared__ float4 qs[8];             // per n: {nax, nay, naz, a2}
    const int t = threadIdx.x;
    const int b    = blockIdx.x >> 9;
    const int half = (blockIdx.x >> 8) & 1;
    const int nc   = blockIdx.x & 255;
    const int nbase = b * 2048 + nc * 8;
    const int mbase = half * 1024 + t * 4;

    float Gx[4], Gy[4], Gz[4], Gr[4];
    {
        float F[12];
        const float4* rp = (const float4*)(pc2 + (size_t)b * 6144 + mbase * 3);
        #pragma unroll
        for (int j = 0; j < 3; j++) {
            const float4 f = rp[j];
            F[4 * j] = f.x; F[4 * j + 1] = f.y;
            F[4 * j + 2] = f.z; F[4 * j + 3] = f.w;
        }
        #pragma unroll
        for (int g = 0; g < 4; g++) {
            Gx[g] = F[3 * g]; Gy[g] = F[3 * g + 1]; Gz[g] = F[3 * g + 2];
            Gr[g] = Gx[g] * Gx[g] + Gy[g] * Gy[g] + Gz[g] * Gz[g];
        }
    }

    if (t < 8) {
        const int n = nbase + t;
        const float x = pc10[3 * n], y = pc10[3 * n + 1], z = pc10[3 * n + 2];
        qs[t] = make_float4(-2.f * x, -2.f * y, -2.f * z, x * x + y * y + z * z);
    }
    const float S = g_scal[2] + 0.5f * g_scal[0] + g_scal[1];
    __syncthreads();

    float* orow = out + (size_t)nbase * 2048 + mbase;
    #pragma unroll
    for (int n = 0; n < 8; n++) {
        const float4 q = qs[n];
        float res[4];
        #pragma unroll
        for (int g = 0; g < 4; g++) {
            const float d2 = fmaf(q.x, Gx[g], fmaf(q.y, Gy[g],
                             fmaf(q.z, Gz[g], Gr[g] + q.w)));
            res[g] = fmaf(0.5f, fsqrt_ap(fmaxf(d2, 0.0f)), S);
        }
        *(float4*)orow = make_float4(res[0], res[1], res[2], res[3]);
        orow += 2048;
    }
}

// ------------------------------ launcher ------------------------------------
extern "C" void kernel_launch(void* const* d_in, const int* in_sizes, int n_in,
                              void* d_out, int out_size)
{
    const float* pc10 = (const float*)d_in[0];
    const float* pc11 = (const float*)d_in[1];
    const float* pc13 = (const float*)d_in[2];
    const float* pc2  = (const float*)d_in[3];
    const float* pc3  = (const float*)d_in[4];
    float* out = (float*)d_out;

    init_kernel<<<1, 32>>>();
    nn_fused<<<416, 256>>>(pc10, pc11, pc2, pc3);
    finalize_kernel<<<2304, 256>>>(pc13);
    out_kernel<<<2048, 256>>>(pc10, pc2, out);
}